// round 8
// baseline (speedup 1.0000x reference)
#include <cuda_runtime.h>
#include <cuda_bf16.h>
#include <stdint.h>
#include <math.h>

// ---------------- problem constants ----------------
#define BB      8
#define TT      4
#define NPTS    1024
#define MPTS    4096
#define CIN     256
#define CORIG   128
#define CCAT    384
#define P1      256
#define P2      256
#define FRAMES  32          // B*T
#define EPS_D   1e-8f
#define EPS_BN  1e-5f

// ---------------- scratch (device globals, no runtime alloc) ----------------
__device__ __align__(16) int   g_idx[FRAMES * MPTS * 3];
__device__ __align__(16) float g_w  [FRAMES * MPTS * 3];
__device__ __align__(16) float g_ZT [(size_t)FRAMES * NPTS * P1];     // [f][n][o]
__device__ __align__(16) float g_y1 [(size_t)FRAMES * MPTS * P1];     // [f][m][o]
__device__ __align__(16) float g_y2 [(size_t)FRAMES * MPTS * P2];     // [f][m][o]
// bf16 split weights, [k][n] layout (n contiguous)
__device__ __align__(16) __nv_bfloat16 g_W1a_h[CIN * P1],   g_W1a_l[CIN * P1];
__device__ __align__(16) __nv_bfloat16 g_W1b_h[CORIG * P1], g_W1b_l[CORIG * P1];
__device__ __align__(16) __nv_bfloat16 g_W2_h [P1 * P2],    g_W2_l [P1 * P2];
__device__ float g_sum1[TT * P1], g_sq1[TT * P1], g_a1[TT * P1], g_b1[TT * P1];
__device__ float g_sum2[TT * P2], g_sq2[TT * P2], g_a2[TT * P2], g_b2[TT * P2];

// ---------------- helpers ----------------
__device__ __forceinline__ uint32_t smem_u32(const void* p) {
    uint32_t a;
    asm("{ .reg .u64 t; cvta.to.shared.u64 t, %1; cvt.u32.u64 %0, t; }" : "=r"(a) : "l"(p));
    return a;
}

#define LDMX4(r, addr) \
    asm volatile("ldmatrix.sync.aligned.m8n8.x4.shared.b16 {%0,%1,%2,%3}, [%4];" \
        : "=r"((r)[0]), "=r"((r)[1]), "=r"((r)[2]), "=r"((r)[3]) : "r"(addr))

#define LDMX4T(r, addr) \
    asm volatile("ldmatrix.sync.aligned.m8n8.x4.trans.shared.b16 {%0,%1,%2,%3}, [%4];" \
        : "=r"((r)[0]), "=r"((r)[1]), "=r"((r)[2]), "=r"((r)[3]) : "r"(addr))

#define MMA_BF16(d, a, b0, b1) \
    asm volatile("mma.sync.aligned.m16n8k16.row.col.f32.bf16.bf16.f32 " \
        "{%0,%1,%2,%3},{%4,%5,%6,%7},{%8,%9},{%0,%1,%2,%3};" \
        : "+f"((d)[0]), "+f"((d)[1]), "+f"((d)[2]), "+f"((d)[3]) \
        : "r"((a)[0]), "r"((a)[1]), "r"((a)[2]), "r"((a)[3]), "r"(b0), "r"(b1))

#define CP_ASYNC16(dst, src) \
    asm volatile("cp.async.cg.shared.global [%0], [%1], 16;" :: "r"(dst), "l"(src))
#define CP_COMMIT()  asm volatile("cp.async.commit_group;" ::: "memory")
#define CP_WAIT0()   asm volatile("cp.async.wait_group 0;" ::: "memory")

__device__ __forceinline__ void split2(float a, float b, uint32_t& h, uint32_t& l) {
    __nv_bfloat162 hb = __floats2bfloat162_rn(a, b);
    float2 hf = __bfloat1622float2(hb);
    __nv_bfloat162 lb = __floats2bfloat162_rn(a - hf.x, b - hf.y);
    h = *reinterpret_cast<uint32_t*>(&hb);
    l = *reinterpret_cast<uint32_t*>(&lb);
}

// ---------------- prep ----------------
__global__ void prep_kernel(const float* __restrict__ W1, const float* __restrict__ W2) {
    int i = blockIdx.x * 256 + threadIdx.x;
    if (i < TT * P1) { g_sum1[i] = 0.f; g_sq1[i] = 0.f; g_sum2[i] = 0.f; g_sq2[i] = 0.f; }
    if (i < P1 * CCAT) {
        int o = i / CCAT, c = i % CCAT;
        float v = W1[i];
        __nv_bfloat16 h = __float2bfloat16_rn(v);
        __nv_bfloat16 l = __float2bfloat16_rn(v - __bfloat162float(h));
        if (c < CIN) { g_W1a_h[c * P1 + o] = h; g_W1a_l[c * P1 + o] = l; }
        else { g_W1b_h[(c - CIN) * P1 + o] = h; g_W1b_l[(c - CIN) * P1 + o] = l; }
    }
    if (i < P2 * P1) {
        int o = i / P1, c = i % P1;
        float v = W2[i];
        __nv_bfloat16 h = __float2bfloat16_rn(v);
        g_W2_h[c * P2 + o] = h;
        g_W2_l[c * P2 + o] = __float2bfloat16_rn(v - __bfloat162float(h));
    }
}

// ---------------- three_nn ----------------
__global__ void knn_kernel(const float* __restrict__ xyzs, const float* __restrict__ oxyzs) {
    __shared__ float sx[NPTS], sy[NPTS], sz[NPTS];
    int f = blockIdx.y;
    const float* p = xyzs + (size_t)f * NPTS * 3;
    for (int i = threadIdx.x; i < NPTS; i += 256) {
        sx[i] = p[3 * i]; sy[i] = p[3 * i + 1]; sz[i] = p[3 * i + 2];
    }
    __syncthreads();
    int m = blockIdx.x * 256 + threadIdx.x;
    const float* q = oxyzs + ((size_t)f * MPTS + m) * 3;
    float qx = q[0], qy = q[1], qz = q[2];
    float b0 = 1e30f, b1 = 1e30f, b2 = 1e30f;
    int   i0 = 0,     i1 = 0,     i2 = 0;
    #pragma unroll 4
    for (int n = 0; n < NPTS; n++) {
        float dx = qx - sx[n], dy = qy - sy[n], dz = qz - sz[n];
        float d = fmaf(dx, dx, fmaf(dy, dy, dz * dz));
        if (d < b2) {
            if (d < b1) {
                b2 = b1; i2 = i1;
                if (d < b0) { b1 = b0; i1 = i0; b0 = d; i0 = n; }
                else        { b1 = d;  i1 = n; }
            } else { b2 = d; i2 = n; }
        }
    }
    float w0 = 1.f / (b0 + EPS_D), w1 = 1.f / (b1 + EPS_D), w2 = 1.f / (b2 + EPS_D);
    float inv = 1.f / (w0 + w1 + w2);
    size_t base = ((size_t)f * MPTS + m) * 3;
    g_idx[base] = i0; g_idx[base + 1] = i1; g_idx[base + 2] = i2;
    g_w[base] = w0 * inv; g_w[base + 1] = w1 * inv; g_w[base + 2] = w2 * inv;
}

// ---------------- HMMA GEMM: C[f][M][256] = A @ W[K][256] ----------------
// CTA 64(M) x 128(N), 8 warps 2x4, warp tile 32x32, K chunk 32, dbl-buffered.
// A via register prefetch (+split,+BN), B via cp.async (pre-split bf16).
// Tight smem so 4 CTAs/SM fit; __launch_bounds__(256,4) targets 64 regs.
// AMODE 0: A [k][m] -> trans ldmatrix ; AMODE 1: A [m][k] + fused BN1+ReLU
// FUSE 1: epilogue combine gather(Z)+stats1 -> y1 ; FUSE 2: store + stats2

template <int K, int AMODE, int FUSE, int MTOT>
__device__ __forceinline__ void gemm_mma(const float* __restrict__ Aall,
                                         const __nv_bfloat16* __restrict__ Bhall,
                                         const __nv_bfloat16* __restrict__ Blall,
                                         float* __restrict__ Call) {
    extern __shared__ char sm[];
    const uint32_t sbase = smem_u32(sm);
    constexpr int NC  = K / 32;
    constexpr int ABF = (AMODE == 1) ? 5120 : 4608;   // bf16 A buf stride (bytes)
    constexpr int OFF_AL = 2 * ABF;
    constexpr int OFF_BH = 4 * ABF;
    constexpr int OFF_BL = OFF_BH + 17408;
    constexpr int OFF_SC = OFF_BL + 17408;            // AMODE1 only

    const int tid = threadIdx.x;
    const int l   = tid & 31;
    const int wid = tid >> 5;
    const int wm  = wid >> 2;       // 0..1
    const int wn  = wid & 3;        // 0..3
    const int f   = blockIdx.z, t = f & 3;
    const int bm  = blockIdx.y * 64;
    const int bn0 = blockIdx.x * 128;
    const float* A = Aall + (size_t)f * MTOT * K;
    float*       C = Call + (size_t)f * MTOT * 256;

    float* s_sc = (float*)(sm + OFF_SC);
    float* s_bi = (float*)(sm + OFF_SC + 1024);
    if (AMODE == 1) {
        s_sc[tid] = g_a1[t * 256 + tid];
        s_bi[tid] = g_b1[t * 256 + tid];
        __syncthreads();
    }

    // global-load assignments
    const int arow = (AMODE == 1) ? (tid >> 2) : (tid >> 3);
    const int acg  = (AMODE == 1) ? ((tid & 3) * 8) : ((tid & 7) * 8);
    const int bk   = tid >> 3, bnc = (tid & 7) * 16;     // B: 16 bf16 = 32B/thread
    const float* Aptr = (AMODE == 1)
        ? A + (size_t)(bm + arow) * K + acg
        : A + (size_t)arow * MTOT + bm + acg;
    const __nv_bfloat16* Bhp = Bhall + (size_t)bk * 256 + bn0 + bnc;
    const __nv_bfloat16* Blp = Blall + (size_t)bk * 256 + bn0 + bnc;
    const uint32_t bsto = (uint32_t)((bk * 136 + bnc) * 2);

    // ldmatrix lane byte-offsets
    const uint32_t aoff = (AMODE == 1)
        ? (uint32_t)(((l & 15) * 40 + (l >> 4) * 8 + wm * 1280) * 2)
        : (uint32_t)((((l & 7) + ((l >> 4) & 1) * 8) * 72 + ((l >> 3) & 1) * 8 + wm * 32) * 2);
    const uint32_t boff = (uint32_t)((((l & 7) + ((l >> 3) & 1) * 8) * 136 +
                                      (l >> 4) * 8 + wn * 32) * 2);

    float acc[2][4][4];
    #pragma unroll
    for (int i = 0; i < 2; i++)
        #pragma unroll
        for (int j = 0; j < 4; j++)
            #pragma unroll
            for (int k = 0; k < 4; k++) acc[i][j][k] = 0.f;

    float4 ra0, ra1;

    auto issueB = [&](int kc, int buf) {
        const char* bhp = (const char*)(Bhp + (size_t)kc * 32 * 256);
        const char* blp = (const char*)(Blp + (size_t)kc * 32 * 256);
        uint32_t dh = sbase + OFF_BH + buf * 8704 + bsto;
        uint32_t dl = sbase + OFF_BL + buf * 8704 + bsto;
        CP_ASYNC16(dh,      bhp);
        CP_ASYNC16(dh + 16, bhp + 16);
        CP_ASYNC16(dl,      blp);
        CP_ASYNC16(dl + 16, blp + 16);
    };
    auto loadA = [&](int kc) {
        const float* ap = (AMODE == 1) ? (Aptr + kc * 32)
                                       : (Aptr + (size_t)kc * 32 * MTOT);
        ra0 = *(const float4*)ap;
        ra1 = *(const float4*)(ap + 4);
    };
    auto storeA = [&](int buf, int kc) {
        float4 v0 = ra0, v1 = ra1;
        if (AMODE == 1) {
            int cc = kc * 32 + acg;
            v0.x = fmaxf(0.f, fmaf(s_sc[cc + 0], v0.x, s_bi[cc + 0]));
            v0.y = fmaxf(0.f, fmaf(s_sc[cc + 1], v0.y, s_bi[cc + 1]));
            v0.z = fmaxf(0.f, fmaf(s_sc[cc + 2], v0.z, s_bi[cc + 2]));
            v0.w = fmaxf(0.f, fmaf(s_sc[cc + 3], v0.w, s_bi[cc + 3]));
            v1.x = fmaxf(0.f, fmaf(s_sc[cc + 4], v1.x, s_bi[cc + 4]));
            v1.y = fmaxf(0.f, fmaf(s_sc[cc + 5], v1.y, s_bi[cc + 5]));
            v1.z = fmaxf(0.f, fmaf(s_sc[cc + 6], v1.z, s_bi[cc + 6]));
            v1.w = fmaxf(0.f, fmaf(s_sc[cc + 7], v1.w, s_bi[cc + 7]));
        }
        uint32_t h0, l0, h1, l1, h2, l2, h3, l3;
        split2(v0.x, v0.y, h0, l0); split2(v0.z, v0.w, h1, l1);
        split2(v1.x, v1.y, h2, l2); split2(v1.z, v1.w, h3, l3);
        uint32_t ao = (uint32_t)(buf * ABF +
            ((AMODE == 1) ? (arow * 40 + acg) : (arow * 72 + acg)) * 2);
        *(uint4*)(sm + ao)          = make_uint4(h0, h1, h2, h3);
        *(uint4*)(sm + OFF_AL + ao) = make_uint4(l0, l1, l2, l3);
    };
    auto compute = [&](int buf) {
        #pragma unroll
        for (int ks = 0; ks < 2; ks++) {
            uint32_t ah[2][4], al[2][4];
            #pragma unroll
            for (int mi = 0; mi < 2; mi++) {
                if (AMODE == 1) {
                    uint32_t ad = sbase + buf * ABF + aoff + mi * 1280 + ks * 32;
                    LDMX4(ah[mi], ad);
                    LDMX4(al[mi], ad + OFF_AL);
                } else {
                    uint32_t ad = sbase + buf * ABF + aoff + mi * 32 + ks * 2304;
                    LDMX4T(ah[mi], ad);
                    LDMX4T(al[mi], ad + OFF_AL);
                }
            }
            #pragma unroll
            for (int nf = 0; nf < 2; nf++) {
                uint32_t bh[4], bl[4];
                uint32_t bd = sbase + OFF_BH + buf * 8704 + boff + nf * 32 + ks * 4352;
                LDMX4T(bh, bd);
                LDMX4T(bl, bd + (OFF_BL - OFF_BH));
                const int n0 = nf * 2, n1 = nf * 2 + 1;
                #pragma unroll
                for (int mi = 0; mi < 2; mi++) {
                    MMA_BF16(acc[mi][n0], ah[mi], bh[0], bh[1]);
                    MMA_BF16(acc[mi][n1], ah[mi], bh[2], bh[3]);
                    MMA_BF16(acc[mi][n0], ah[mi], bl[0], bl[1]);
                    MMA_BF16(acc[mi][n1], ah[mi], bl[2], bl[3]);
                    MMA_BF16(acc[mi][n0], al[mi], bh[0], bh[1]);
                    MMA_BF16(acc[mi][n1], al[mi], bh[2], bh[3]);
                }
            }
        }
    };

    issueB(0, 0); CP_COMMIT();
    loadA(0); storeA(0, 0);
    CP_WAIT0();
    __syncthreads();
    for (int kc = 0; kc < NC; kc++) {
        if (kc + 1 < NC) {
            issueB(kc + 1, (kc + 1) & 1); CP_COMMIT();
            loadA(kc + 1);
        }
        compute(kc & 1);
        if (kc + 1 < NC) {
            storeA((kc + 1) & 1, kc + 1);
            CP_WAIT0();
            __syncthreads();
        }
    }

    if (FUSE == 1) {
        // stage acc tile to smem fp32 [64][136], then combine gather(Z)+stats1 -> y1
        __syncthreads();
        float* smf = (float*)sm;
        #pragma unroll
        for (int ni = 0; ni < 4; ni++) {
            int c = wn * 32 + ni * 8 + (l & 3) * 2;
            #pragma unroll
            for (int mi = 0; mi < 2; mi++) {
                int r = wm * 32 + mi * 16 + (l >> 2);
                *(float2*)&smf[r * 136 + c]       = make_float2(acc[mi][ni][0], acc[mi][ni][1]);
                *(float2*)&smf[(r + 8) * 136 + c] = make_float2(acc[mi][ni][2], acc[mi][ni][3]);
            }
        }
        __syncthreads();
        const int oc = tid & 127, half = tid >> 7;
        const int o  = bn0 + oc;
        const float* Z = g_ZT + (size_t)f * NPTS * 256;
        float s = 0.f, q = 0.f;
        #pragma unroll 4
        for (int rr = 0; rr < 32; rr++) {
            int r = half * 32 + rr;
            int m = bm + r;
            size_t ib = ((size_t)f * MPTS + m) * 3;
            int   i0 = g_idx[ib], i1 = g_idx[ib + 1], i2 = g_idx[ib + 2];
            float w0 = g_w[ib],   w1 = g_w[ib + 1],   w2 = g_w[ib + 2];
            float v = smf[r * 136 + oc];
            v = fmaf(w0, Z[(size_t)i0 * 256 + o], v);
            v = fmaf(w1, Z[(size_t)i1 * 256 + o], v);
            v = fmaf(w2, Z[(size_t)i2 * 256 + o], v);
            g_y1[((size_t)f * MPTS + m) * 256 + o] = v;
            s += v; q = fmaf(v, v, q);
        }
        atomicAdd(&g_sum1[t * 256 + o], s);
        atomicAdd(&g_sq1 [t * 256 + o], q);
    } else {
        #pragma unroll
        for (int ni = 0; ni < 4; ni++) {
            int col = bn0 + wn * 32 + ni * 8 + (l & 3) * 2;
            float s0 = 0.f, q0 = 0.f, s1 = 0.f, q1 = 0.f;
            #pragma unroll
            for (int mi = 0; mi < 2; mi++) {
                int row = bm + wm * 32 + mi * 16 + (l >> 2);
                float v0 = acc[mi][ni][0], v1 = acc[mi][ni][1];
                float v2 = acc[mi][ni][2], v3 = acc[mi][ni][3];
                float* cp = C + (size_t)row * 256 + col;
                *(float2*)cp          = make_float2(v0, v1);
                *(float2*)(cp + 2048) = make_float2(v2, v3);
                if (FUSE == 2) {
                    s0 += v0 + v2; s1 += v1 + v3;
                    q0 += fmaf(v0, v0, v2 * v2);
                    q1 += fmaf(v1, v1, v3 * v3);
                }
            }
            if (FUSE == 2) {
                #pragma unroll
                for (int d = 4; d < 32; d <<= 1) {
                    s0 += __shfl_xor_sync(0xffffffffu, s0, d);
                    s1 += __shfl_xor_sync(0xffffffffu, s1, d);
                    q0 += __shfl_xor_sync(0xffffffffu, q0, d);
                    q1 += __shfl_xor_sync(0xffffffffu, q1, d);
                }
                if (l < 4) {
                    atomicAdd(&g_sum2[t * 256 + col],     s0);
                    atomicAdd(&g_sum2[t * 256 + col + 1], s1);
                    atomicAdd(&g_sq2 [t * 256 + col],     q0);
                    atomicAdd(&g_sq2 [t * 256 + col + 1], q1);
                }
            }
        }
    }
}

#define SMEM_A0 53248     // 4*4608 + 4*8704
#define SMEM_A1 57344     // 4*5120 + 4*8704 + 2048

__global__ void __launch_bounds__(256, 4) gemmZ_mma(const float* __restrict__ feats) {
    gemm_mma<CIN, 0, 0, NPTS>(feats, g_W1a_h, g_W1a_l, g_ZT);
}
__global__ void __launch_bounds__(256, 4) gemmB_mma(const float* __restrict__ ofeat) {
    gemm_mma<CORIG, 0, 1, MPTS>(ofeat, g_W1b_h, g_W1b_l, g_y1);
}
__global__ void __launch_bounds__(256, 4) gemm2_mma() {
    gemm_mma<P1, 1, 2, MPTS>(g_y1, g_W2_h, g_W2_l, g_y2);
}

// ---------------- finalize BN coefficients ----------------
__global__ void finalize_kernel(int which, const float* __restrict__ gamma,
                                const float* __restrict__ beta) {
    int i = blockIdx.x * 256 + threadIdx.x;
    if (i >= TT * P1) return;
    const float rcnt = 1.0f / (float)(BB * MPTS);
    float sum = (which == 1) ? g_sum1[i] : g_sum2[i];
    float sq  = (which == 1) ? g_sq1[i]  : g_sq2[i];
    float mean = sum * rcnt;
    float var  = fmaf(-mean, mean, sq * rcnt);
    int o = i & 255;
    float a = gamma[o] * rsqrtf(var + EPS_BN);
    float b = fmaf(-mean, a, beta[o]);
    if (which == 1) { g_a1[i] = a; g_b1[i] = b; }
    else            { g_a2[i] = a; g_b2[i] = b; }
}

// ---------------- output: BN2+ReLU + transpose [f][m][o] -> [f][o][m] ----------------
__global__ void output_kernel(float* __restrict__ out) {
    __shared__ float tile[32][33];
    int f = blockIdx.z, t = f & 3;
    int m0 = blockIdx.x * 32, o0 = blockIdx.y * 32;
    int tx = threadIdx.x, ty = threadIdx.y;
    #pragma unroll
    for (int i = ty; i < 32; i += 8) {
        int o = o0 + tx;
        float v = g_y2[((size_t)f * MPTS + m0 + i) * P2 + o];
        tile[i][tx] = fmaxf(0.f, fmaf(g_a2[t * P2 + o], v, g_b2[t * P2 + o]));
    }
    __syncthreads();
    #pragma unroll
    for (int i = ty; i < 32; i += 8)
        out[((size_t)f * P2 + o0 + i) * MPTS + m0 + tx] = tile[tx][i];
}

// ---------------- launch ----------------
extern "C" void kernel_launch(void* const* d_in, const int* in_sizes, int n_in,
                              void* d_out, int out_size) {
    const float* xyzs   = (const float*)d_in[0];
    const float* oxyzs  = (const float*)d_in[1];
    const float* feats  = (const float*)d_in[2];
    const float* ofeat  = (const float*)d_in[3];
    const float* W1     = (const float*)d_in[4];
    const float* gamma1 = (const float*)d_in[5];
    const float* beta1  = (const float*)d_in[6];
    const float* W2     = (const float*)d_in[7];
    const float* gamma2 = (const float*)d_in[8];
    const float* beta2  = (const float*)d_in[9];
    float* out = (float*)d_out;

    (void)cudaFuncSetAttribute(gemmZ_mma, cudaFuncAttributeMaxDynamicSharedMemorySize, SMEM_A0);
    (void)cudaFuncSetAttribute(gemmB_mma, cudaFuncAttributeMaxDynamicSharedMemorySize, SMEM_A0);
    (void)cudaFuncSetAttribute(gemm2_mma, cudaFuncAttributeMaxDynamicSharedMemorySize, SMEM_A1);

    const int xyz_elems = FRAMES * MPTS * 3;
    const int x_elems   = FRAMES * P2 * MPTS;
    float* out_x = out;
    if (out_size >= xyz_elems + x_elems) {
        cudaMemcpyAsync(out, oxyzs, (size_t)xyz_elems * sizeof(float),
                        cudaMemcpyDeviceToDevice, 0);
        out_x = out + xyz_elems;
    }

    prep_kernel<<<384, 256>>>(W1, W2);
    knn_kernel<<<dim3(MPTS / 256, FRAMES), 256>>>(xyzs, oxyzs);

    gemmZ_mma<<<dim3(2, NPTS / 64, FRAMES), 256, SMEM_A0>>>(feats);   // Z = feats^T @ W1a
    gemmB_mma<<<dim3(2, MPTS / 64, FRAMES), 256, SMEM_A0>>>(ofeat);   // y1 + gather(Z); stats1
    finalize_kernel<<<4, 256>>>(1, gamma1, beta1);

    gemm2_mma<<<dim3(2, MPTS / 64, FRAMES), 256, SMEM_A1>>>();        // y2 = relu(bn1(y1)) @ W2; stats2
    finalize_kernel<<<4, 256>>>(2, gamma2, beta2);

    output_kernel<<<dim3(MPTS / 32, P2 / 32, FRAMES), dim3(32, 8)>>>(out_x);
}

// round 9
// speedup vs baseline: 1.2522x; 1.2522x over previous
#include <cuda_runtime.h>
#include <cuda_bf16.h>
#include <stdint.h>
#include <math.h>

// ---------------- problem constants ----------------
#define BB      8
#define TT      4
#define NPTS    1024
#define MPTS    4096
#define CIN     256
#define CORIG   128
#define CCAT    384
#define P1      256
#define P2      256
#define FRAMES  32          // B*T
#define EPS_D   1e-8f
#define EPS_BN  1e-5f

// ---------------- scratch (device globals, no runtime alloc) ----------------
__device__ __align__(16) int   g_idx[FRAMES * MPTS * 3];
__device__ __align__(16) float g_w  [FRAMES * MPTS * 3];
__device__ __align__(16) float g_ZT [(size_t)FRAMES * NPTS * P1];     // [f][n][o]
__device__ __align__(16) float g_y1 [(size_t)FRAMES * MPTS * P1];     // [f][m][o]
__device__ __align__(16) float g_y2 [(size_t)FRAMES * MPTS * P2];     // [f][m][o]
// bf16 split weights, [k][n] layout (n contiguous)
__device__ __align__(16) __nv_bfloat16 g_W1a_h[CIN * P1],   g_W1a_l[CIN * P1];
__device__ __align__(16) __nv_bfloat16 g_W1b_h[CORIG * P1], g_W1b_l[CORIG * P1];
__device__ __align__(16) __nv_bfloat16 g_W2_h [P1 * P2],    g_W2_l [P1 * P2];
__device__ float g_sum1[TT * P1], g_sq1[TT * P1], g_a1[TT * P1], g_b1[TT * P1];
__device__ float g_sum2[TT * P2], g_sq2[TT * P2], g_a2[TT * P2], g_b2[TT * P2];

// ---------------- helpers ----------------
__device__ __forceinline__ uint32_t smem_u32(const void* p) {
    uint32_t a;
    asm("{ .reg .u64 t; cvta.to.shared.u64 t, %1; cvt.u32.u64 %0, t; }" : "=r"(a) : "l"(p));
    return a;
}

#define LDMX4(r, addr) \
    asm volatile("ldmatrix.sync.aligned.m8n8.x4.shared.b16 {%0,%1,%2,%3}, [%4];" \
        : "=r"((r)[0]), "=r"((r)[1]), "=r"((r)[2]), "=r"((r)[3]) : "r"(addr))

#define LDMX4T(r, addr) \
    asm volatile("ldmatrix.sync.aligned.m8n8.x4.trans.shared.b16 {%0,%1,%2,%3}, [%4];" \
        : "=r"((r)[0]), "=r"((r)[1]), "=r"((r)[2]), "=r"((r)[3]) : "r"(addr))

#define MMA_BF16(d, a, b0, b1) \
    asm volatile("mma.sync.aligned.m16n8k16.row.col.f32.bf16.bf16.f32 " \
        "{%0,%1,%2,%3},{%4,%5,%6,%7},{%8,%9},{%0,%1,%2,%3};" \
        : "+f"((d)[0]), "+f"((d)[1]), "+f"((d)[2]), "+f"((d)[3]) \
        : "r"((a)[0]), "r"((a)[1]), "r"((a)[2]), "r"((a)[3]), "r"(b0), "r"(b1))

#define CP_ASYNC16(dst, src) \
    asm volatile("cp.async.cg.shared.global [%0], [%1], 16;" :: "r"(dst), "l"(src))
#define CP_COMMIT()  asm volatile("cp.async.commit_group;" ::: "memory")
#define CP_WAIT0()   asm volatile("cp.async.wait_group 0;" ::: "memory")
#define CP_WAIT1()   asm volatile("cp.async.wait_group 1;" ::: "memory")

__device__ __forceinline__ void split2(float a, float b, uint32_t& h, uint32_t& l) {
    __nv_bfloat162 hb = __floats2bfloat162_rn(a, b);
    float2 hf = __bfloat1622float2(hb);
    __nv_bfloat162 lb = __floats2bfloat162_rn(a - hf.x, b - hf.y);
    h = *reinterpret_cast<uint32_t*>(&hb);
    l = *reinterpret_cast<uint32_t*>(&lb);
}

// ---------------- prep ----------------
__global__ void prep_kernel(const float* __restrict__ W1, const float* __restrict__ W2) {
    int i = blockIdx.x * 256 + threadIdx.x;
    if (i < TT * P1) { g_sum1[i] = 0.f; g_sq1[i] = 0.f; g_sum2[i] = 0.f; g_sq2[i] = 0.f; }
    if (i < P1 * CCAT) {
        int o = i / CCAT, c = i % CCAT;
        float v = W1[i];
        __nv_bfloat16 h = __float2bfloat16_rn(v);
        __nv_bfloat16 l = __float2bfloat16_rn(v - __bfloat162float(h));
        if (c < CIN) { g_W1a_h[c * P1 + o] = h; g_W1a_l[c * P1 + o] = l; }
        else { g_W1b_h[(c - CIN) * P1 + o] = h; g_W1b_l[(c - CIN) * P1 + o] = l; }
    }
    if (i < P2 * P1) {
        int o = i / P1, c = i % P1;
        float v = W2[i];
        __nv_bfloat16 h = __float2bfloat16_rn(v);
        g_W2_h[c * P2 + o] = h;
        g_W2_l[c * P2 + o] = __float2bfloat16_rn(v - __bfloat162float(h));
    }
}

// ---------------- three_nn ----------------
__global__ void knn_kernel(const float* __restrict__ xyzs, const float* __restrict__ oxyzs) {
    __shared__ float sx[NPTS], sy[NPTS], sz[NPTS];
    int f = blockIdx.y;
    const float* p = xyzs + (size_t)f * NPTS * 3;
    for (int i = threadIdx.x; i < NPTS; i += 256) {
        sx[i] = p[3 * i]; sy[i] = p[3 * i + 1]; sz[i] = p[3 * i + 2];
    }
    __syncthreads();
    int m = blockIdx.x * 256 + threadIdx.x;
    const float* q = oxyzs + ((size_t)f * MPTS + m) * 3;
    float qx = q[0], qy = q[1], qz = q[2];
    float b0 = 1e30f, b1 = 1e30f, b2 = 1e30f;
    int   i0 = 0,     i1 = 0,     i2 = 0;
    #pragma unroll 4
    for (int n = 0; n < NPTS; n++) {
        float dx = qx - sx[n], dy = qy - sy[n], dz = qz - sz[n];
        float d = fmaf(dx, dx, fmaf(dy, dy, dz * dz));
        if (d < b2) {
            if (d < b1) {
                b2 = b1; i2 = i1;
                if (d < b0) { b1 = b0; i1 = i0; b0 = d; i0 = n; }
                else        { b1 = d;  i1 = n; }
            } else { b2 = d; i2 = n; }
        }
    }
    float w0 = 1.f / (b0 + EPS_D), w1 = 1.f / (b1 + EPS_D), w2 = 1.f / (b2 + EPS_D);
    float inv = 1.f / (w0 + w1 + w2);
    size_t base = ((size_t)f * MPTS + m) * 3;
    g_idx[base] = i0; g_idx[base + 1] = i1; g_idx[base + 2] = i2;
    g_w[base] = w0 * inv; g_w[base + 1] = w1 * inv; g_w[base + 2] = w2 * inv;
}

// ---------------- HMMA GEMM: C[f][M][256] = A @ W[K][256] ----------------
// CTA 64(M) x 128(N), 8 warps 2x4, warp tile 32x32, K chunk 32, dbl-buffered.
// AMODE 0: A [k][m], A via cp.async + smem transform (split). 70656 B smem, occ3.
// AMODE 1: A [m][k], register-prefetch A with fused BN1+ReLU.  57344 B smem, occ3.
// compute(): MMAs grouped by split-term -> dependency distance 8.
// FUSE 1: epilogue combine gather(Z)+stats1 -> y1 ; FUSE 2: store + stats2

template <int K, int AMODE, int FUSE, int MTOT>
__device__ __forceinline__ void gemm_mma(const float* __restrict__ Aall,
                                         const __nv_bfloat16* __restrict__ Bhall,
                                         const __nv_bfloat16* __restrict__ Blall,
                                         float* __restrict__ Call) {
    extern __shared__ char sm[];
    const uint32_t sbase = smem_u32(sm);
    constexpr int NC  = K / 32;
    constexpr int ABF = (AMODE == 1) ? 5120 : 4608;   // bf16 A buf stride (bytes)
    constexpr int AFB = 8704;                          // fp32 A buf stride (AMODE0)
    constexpr int OFF_AL = 2 * ABF;
    constexpr int OFF_AF = 4 * ABF;                    // AMODE0 only
    constexpr int OFF_BH = (AMODE == 0) ? (OFF_AF + 2 * AFB) : (4 * ABF);
    constexpr int OFF_BL = OFF_BH + 17408;
    constexpr int OFF_SC = OFF_BL + 17408;             // AMODE1 only

    const int tid = threadIdx.x;
    const int l   = tid & 31;
    const int wid = tid >> 5;
    const int wm  = wid >> 2;       // 0..1
    const int wn  = wid & 3;        // 0..3
    const int f   = blockIdx.z, t = f & 3;
    const int bm  = blockIdx.y * 64;
    const int bn0 = blockIdx.x * 128;
    const float* A = Aall + (size_t)f * MTOT * K;
    float*       C = Call + (size_t)f * MTOT * 256;

    float* s_sc = (float*)(sm + OFF_SC);
    float* s_bi = (float*)(sm + OFF_SC + 1024);
    if (AMODE == 1) {
        s_sc[tid] = g_a1[t * 256 + tid];
        s_bi[tid] = g_b1[t * 256 + tid];
        __syncthreads();
    }

    // ldmatrix lane byte-offsets
    const uint32_t aoff = (AMODE == 1)
        ? (uint32_t)((l & 15) * 80 + (l >> 4) * 16 + wm * 2560)
        : (uint32_t)(((l & 7) + ((l >> 4) & 1) * 8) * 144 + ((l >> 3) & 1) * 16 + wm * 64);
    const uint32_t boff = (uint32_t)((((l & 7) + ((l >> 3) & 1) * 8) * 136 +
                                      (l >> 4) * 8 + wn * 32) * 2);

    float acc[2][4][4];
    #pragma unroll
    for (int i = 0; i < 2; i++)
        #pragma unroll
        for (int j = 0; j < 4; j++)
            #pragma unroll
            for (int k = 0; k < 4; k++) acc[i][j][k] = 0.f;

    float4 ra0, ra1;    // AMODE1 register prefetch

    auto issueB = [&](int kc, int bb) {
        int r  = tid >> 3;
        int ce = (tid & 7) * 16;
        const __nv_bfloat16* sh = Bhall + (size_t)(kc * 32 + r) * 256 + bn0 + ce;
        const __nv_bfloat16* sl = Blall + (size_t)(kc * 32 + r) * 256 + bn0 + ce;
        uint32_t dh = sbase + OFF_BH + bb * 8704 + (uint32_t)(r * 272 + ce * 2);
        uint32_t dl = dh + (OFF_BL - OFF_BH);
        CP_ASYNC16(dh,      sh);
        CP_ASYNC16(dh + 16, sh + 8);
        CP_ASYNC16(dl,      sl);
        CP_ASYNC16(dl + 16, sl + 8);
    };
    // ---- AMODE0: A fp32 cp.async + transform ----
    auto issueAf = [&](int kc, int fb) {
        int r = tid >> 3;
        const float* s = A + (size_t)(kc * 32 + r) * MTOT + bm + (tid & 7) * 8;
        uint32_t dd = sbase + OFF_AF + fb * AFB + (uint32_t)(r * 272 + (tid & 7) * 32);
        CP_ASYNC16(dd, s);
        CP_ASYNC16(dd + 16, s + 4);
    };
    auto transform = [&](int fb, int ab) {
        #pragma unroll
        for (int g = 0; g < 2; g++) {
            int r = (tid >> 4) + g * 16;
            uint32_t srcb = (uint32_t)(OFF_AF + fb * AFB + r * 272 + (tid & 15) * 16);
            float4 v = *(const float4*)(sm + srcb);
            uint32_t h0, l0, h1, l1;
            split2(v.x, v.y, h0, l0); split2(v.z, v.w, h1, l1);
            uint32_t dst = (uint32_t)(ab * ABF + r * 144 + (tid & 15) * 8);
            *(uint2*)(sm + dst)          = make_uint2(h0, h1);
            *(uint2*)(sm + OFF_AL + dst) = make_uint2(l0, l1);
        }
    };
    // ---- AMODE1: register prefetch + fused BN ----
    auto loadA = [&](int kc) {
        const float* ap = A + (size_t)(bm + (tid >> 2)) * K + kc * 32 + (tid & 3) * 8;
        ra0 = *(const float4*)ap;
        ra1 = *(const float4*)(ap + 4);
    };
    auto storeA = [&](int buf, int kc) {
        float4 v0 = ra0, v1 = ra1;
        int cc = kc * 32 + (tid & 3) * 8;
        v0.x = fmaxf(0.f, fmaf(s_sc[cc + 0], v0.x, s_bi[cc + 0]));
        v0.y = fmaxf(0.f, fmaf(s_sc[cc + 1], v0.y, s_bi[cc + 1]));
        v0.z = fmaxf(0.f, fmaf(s_sc[cc + 2], v0.z, s_bi[cc + 2]));
        v0.w = fmaxf(0.f, fmaf(s_sc[cc + 3], v0.w, s_bi[cc + 3]));
        v1.x = fmaxf(0.f, fmaf(s_sc[cc + 4], v1.x, s_bi[cc + 4]));
        v1.y = fmaxf(0.f, fmaf(s_sc[cc + 5], v1.y, s_bi[cc + 5]));
        v1.z = fmaxf(0.f, fmaf(s_sc[cc + 6], v1.z, s_bi[cc + 6]));
        v1.w = fmaxf(0.f, fmaf(s_sc[cc + 7], v1.w, s_bi[cc + 7]));
        uint32_t h0, l0, h1, l1, h2, l2, h3, l3;
        split2(v0.x, v0.y, h0, l0); split2(v0.z, v0.w, h1, l1);
        split2(v1.x, v1.y, h2, l2); split2(v1.z, v1.w, h3, l3);
        uint32_t ao = (uint32_t)(buf * ABF + (tid >> 2) * 80 + (tid & 3) * 16);
        *(uint4*)(sm + ao)          = make_uint4(h0, h1, h2, h3);
        *(uint4*)(sm + OFF_AL + ao) = make_uint4(l0, l1, l2, l3);
    };
    // ---- compute: term-grouped MMAs (dependency distance 8) ----
    auto compute = [&](int buf) {
        #pragma unroll
        for (int ks = 0; ks < 2; ks++) {
            uint32_t ah[2][4], al[2][4], bh[2][4], bl[2][4];
            #pragma unroll
            for (int mi = 0; mi < 2; mi++) {
                if (AMODE == 1) {
                    uint32_t ad = sbase + buf * ABF + aoff + mi * 1280 + ks * 32;
                    LDMX4(ah[mi], ad);
                    LDMX4(al[mi], ad + OFF_AL);
                } else {
                    uint32_t ad = sbase + buf * ABF + aoff + mi * 32 + ks * 2304;
                    LDMX4T(ah[mi], ad);
                    LDMX4T(al[mi], ad + OFF_AL);
                }
            }
            #pragma unroll
            for (int nf = 0; nf < 2; nf++) {
                uint32_t bd = sbase + OFF_BH + buf * 8704 + boff + nf * 32 + ks * 4352;
                LDMX4T(bh[nf], bd);
                LDMX4T(bl[nf], bd + (OFF_BL - OFF_BH));
            }
            // term 1: ah x bh
            #pragma unroll
            for (int mi = 0; mi < 2; mi++)
                #pragma unroll
                for (int nf = 0; nf < 2; nf++) {
                    MMA_BF16(acc[mi][nf * 2],     ah[mi], bh[nf][0], bh[nf][1]);
                    MMA_BF16(acc[mi][nf * 2 + 1], ah[mi], bh[nf][2], bh[nf][3]);
                }
            // term 2: ah x bl
            #pragma unroll
            for (int mi = 0; mi < 2; mi++)
                #pragma unroll
                for (int nf = 0; nf < 2; nf++) {
                    MMA_BF16(acc[mi][nf * 2],     ah[mi], bl[nf][0], bl[nf][1]);
                    MMA_BF16(acc[mi][nf * 2 + 1], ah[mi], bl[nf][2], bl[nf][3]);
                }
            // term 3: al x bh
            #pragma unroll
            for (int mi = 0; mi < 2; mi++)
                #pragma unroll
                for (int nf = 0; nf < 2; nf++) {
                    MMA_BF16(acc[mi][nf * 2],     al[mi], bh[nf][0], bh[nf][1]);
                    MMA_BF16(acc[mi][nf * 2 + 1], al[mi], bh[nf][2], bh[nf][3]);
                }
        }
    };

    if (AMODE == 0) {
        // 3-stage: Af32(0) | B(0)+Af32(1) in flight; transform feeds bf16 bufs
        issueAf(0, 0); CP_COMMIT();
        issueB(0, 0); issueAf(1, 1); CP_COMMIT();
        CP_WAIT1();
        __syncthreads();
        transform(0, 0);
        for (int kc = 0; kc < NC; kc++) {
            CP_WAIT0();
            __syncthreads();
            if (kc + 1 < NC) {
                transform((kc + 1) & 1, (kc + 1) & 1);
                issueB(kc + 1, (kc + 1) & 1);
                if (kc + 2 < NC) issueAf(kc + 2, kc & 1);
                CP_COMMIT();
            }
            compute(kc & 1);
        }
    } else {
        issueB(0, 0); CP_COMMIT();
        loadA(0); storeA(0, 0);
        CP_WAIT0();
        __syncthreads();
        for (int kc = 0; kc < NC; kc++) {
            if (kc + 1 < NC) {
                issueB(kc + 1, (kc + 1) & 1); CP_COMMIT();
                loadA(kc + 1);
            }
            compute(kc & 1);
            if (kc + 1 < NC) {
                storeA((kc + 1) & 1, kc + 1);
                CP_WAIT0();
                __syncthreads();
            }
        }
    }

    if (FUSE == 1) {
        // stage acc tile to smem fp32 [64][136], then combine gather(Z)+stats1 -> y1
        __syncthreads();
        float* smf = (float*)sm;
        #pragma unroll
        for (int ni = 0; ni < 4; ni++) {
            int c = wn * 32 + ni * 8 + (l & 3) * 2;
            #pragma unroll
            for (int mi = 0; mi < 2; mi++) {
                int r = wm * 32 + mi * 16 + (l >> 2);
                *(float2*)&smf[r * 136 + c]       = make_float2(acc[mi][ni][0], acc[mi][ni][1]);
                *(float2*)&smf[(r + 8) * 136 + c] = make_float2(acc[mi][ni][2], acc[mi][ni][3]);
            }
        }
        __syncthreads();
        const int oc = tid & 127, half = tid >> 7;
        const int o  = bn0 + oc;
        const float* Z = g_ZT + (size_t)f * NPTS * 256;
        float s = 0.f, q = 0.f;
        #pragma unroll 4
        for (int rr = 0; rr < 32; rr++) {
            int r = half * 32 + rr;
            int m = bm + r;
            size_t ib = ((size_t)f * MPTS + m) * 3;
            int   i0 = g_idx[ib], i1 = g_idx[ib + 1], i2 = g_idx[ib + 2];
            float w0 = g_w[ib],   w1 = g_w[ib + 1],   w2 = g_w[ib + 2];
            float v = smf[r * 136 + oc];
            v = fmaf(w0, Z[(size_t)i0 * 256 + o], v);
            v = fmaf(w1, Z[(size_t)i1 * 256 + o], v);
            v = fmaf(w2, Z[(size_t)i2 * 256 + o], v);
            g_y1[((size_t)f * MPTS + m) * 256 + o] = v;
            s += v; q = fmaf(v, v, q);
        }
        atomicAdd(&g_sum1[t * 256 + o], s);
        atomicAdd(&g_sq1 [t * 256 + o], q);
    } else {
        #pragma unroll
        for (int ni = 0; ni < 4; ni++) {
            int col = bn0 + wn * 32 + ni * 8 + (l & 3) * 2;
            float s0 = 0.f, q0 = 0.f, s1 = 0.f, q1 = 0.f;
            #pragma unroll
            for (int mi = 0; mi < 2; mi++) {
                int row = bm + wm * 32 + mi * 16 + (l >> 2);
                float v0 = acc[mi][ni][0], v1 = acc[mi][ni][1];
                float v2 = acc[mi][ni][2], v3 = acc[mi][ni][3];
                float* cp = C + (size_t)row * 256 + col;
                *(float2*)cp          = make_float2(v0, v1);
                *(float2*)(cp + 2048) = make_float2(v2, v3);
                if (FUSE == 2) {
                    s0 += v0 + v2; s1 += v1 + v3;
                    q0 += fmaf(v0, v0, v2 * v2);
                    q1 += fmaf(v1, v1, v3 * v3);
                }
            }
            if (FUSE == 2) {
                #pragma unroll
                for (int d = 4; d < 32; d <<= 1) {
                    s0 += __shfl_xor_sync(0xffffffffu, s0, d);
                    s1 += __shfl_xor_sync(0xffffffffu, s1, d);
                    q0 += __shfl_xor_sync(0xffffffffu, q0, d);
                    q1 += __shfl_xor_sync(0xffffffffu, q1, d);
                }
                if (l < 4) {
                    atomicAdd(&g_sum2[t * 256 + col],     s0);
                    atomicAdd(&g_sum2[t * 256 + col + 1], s1);
                    atomicAdd(&g_sq2 [t * 256 + col],     q0);
                    atomicAdd(&g_sq2 [t * 256 + col + 1], q1);
                }
            }
        }
    }
}

#define SMEM_A0 70656     // 4*4608 + 2*8704 + 4*8704
#define SMEM_A1 57344     // 4*5120 + 4*8704 + 2048

__global__ void __launch_bounds__(256, 3) gemmZ_mma(const float* __restrict__ feats) {
    gemm_mma<CIN, 0, 0, NPTS>(feats, g_W1a_h, g_W1a_l, g_ZT);
}
__global__ void __launch_bounds__(256, 3) gemmB_mma(const float* __restrict__ ofeat) {
    gemm_mma<CORIG, 0, 1, MPTS>(ofeat, g_W1b_h, g_W1b_l, g_y1);
}
__global__ void __launch_bounds__(256, 3) gemm2_mma() {
    gemm_mma<P1, 1, 2, MPTS>(g_y1, g_W2_h, g_W2_l, g_y2);
}

// ---------------- finalize BN coefficients ----------------
__global__ void finalize_kernel(int which, const float* __restrict__ gamma,
                                const float* __restrict__ beta) {
    int i = blockIdx.x * 256 + threadIdx.x;
    if (i >= TT * P1) return;
    const float rcnt = 1.0f / (float)(BB * MPTS);
    float sum = (which == 1) ? g_sum1[i] : g_sum2[i];
    float sq  = (which == 1) ? g_sq1[i]  : g_sq2[i];
    float mean = sum * rcnt;
    float var  = fmaf(-mean, mean, sq * rcnt);
    int o = i & 255;
    float a = gamma[o] * rsqrtf(var + EPS_BN);
    float b = fmaf(-mean, a, beta[o]);
    if (which == 1) { g_a1[i] = a; g_b1[i] = b; }
    else            { g_a2[i] = a; g_b2[i] = b; }
}

// ---------------- output: BN2+ReLU + transpose [f][m][o] -> [f][o][m] ----------------
__global__ void output_kernel(float* __restrict__ out) {
    __shared__ float tile[32][33];
    int f = blockIdx.z, t = f & 3;
    int m0 = blockIdx.x * 32, o0 = blockIdx.y * 32;
    int tx = threadIdx.x, ty = threadIdx.y;
    #pragma unroll
    for (int i = ty; i < 32; i += 8) {
        int o = o0 + tx;
        float v = g_y2[((size_t)f * MPTS + m0 + i) * P2 + o];
        tile[i][tx] = fmaxf(0.f, fmaf(g_a2[t * P2 + o], v, g_b2[t * P2 + o]));
    }
    __syncthreads();
    #pragma unroll
    for (int i = ty; i < 32; i += 8)
        out[((size_t)f * P2 + o0 + i) * MPTS + m0 + tx] = tile[tx][i];
}

// ---------------- launch ----------------
extern "C" void kernel_launch(void* const* d_in, const int* in_sizes, int n_in,
                              void* d_out, int out_size) {
    const float* xyzs   = (const float*)d_in[0];
    const float* oxyzs  = (const float*)d_in[1];
    const float* feats  = (const float*)d_in[2];
    const float* ofeat  = (const float*)d_in[3];
    const float* W1     = (const float*)d_in[4];
    const float* gamma1 = (const float*)d_in[5];
    const float* beta1  = (const float*)d_in[6];
    const float* W2     = (const float*)d_in[7];
    const float* gamma2 = (const float*)d_in[8];
    const float* beta2  = (const float*)d_in[9];
    float* out = (float*)d_out;

    (void)cudaFuncSetAttribute(gemmZ_mma, cudaFuncAttributeMaxDynamicSharedMemorySize, SMEM_A0);
    (void)cudaFuncSetAttribute(gemmB_mma, cudaFuncAttributeMaxDynamicSharedMemorySize, SMEM_A0);
    (void)cudaFuncSetAttribute(gemm2_mma, cudaFuncAttributeMaxDynamicSharedMemorySize, SMEM_A1);

    const int xyz_elems = FRAMES * MPTS * 3;
    const int x_elems   = FRAMES * P2 * MPTS;
    float* out_x = out;
    if (out_size >= xyz_elems + x_elems) {
        cudaMemcpyAsync(out, oxyzs, (size_t)xyz_elems * sizeof(float),
                        cudaMemcpyDeviceToDevice, 0);
        out_x = out + xyz_elems;
    }

    prep_kernel<<<384, 256>>>(W1, W2);
    knn_kernel<<<dim3(MPTS / 256, FRAMES), 256>>>(xyzs, oxyzs);

    gemmZ_mma<<<dim3(2, NPTS / 64, FRAMES), 256, SMEM_A0>>>(feats);   // Z = feats^T @ W1a
    gemmB_mma<<<dim3(2, MPTS / 64, FRAMES), 256, SMEM_A0>>>(ofeat);   // y1 + gather(Z); stats1
    finalize_kernel<<<4, 256>>>(1, gamma1, beta1);

    gemm2_mma<<<dim3(2, MPTS / 64, FRAMES), 256, SMEM_A1>>>();        // y2 = relu(bn1(y1)) @ W2; stats2
    finalize_kernel<<<4, 256>>>(2, gamma2, beta2);

    output_kernel<<<dim3(MPTS / 32, P2 / 32, FRAMES), dim3(32, 8)>>>(out_x);
}

// round 10
// speedup vs baseline: 1.4012x; 1.1190x over previous
#include <cuda_runtime.h>
#include <cuda_fp16.h>
#include <stdint.h>
#include <math.h>

// ---------------- problem constants ----------------
#define BB      8
#define TT      4
#define NPTS    1024
#define MPTS    4096
#define CIN     256
#define CORIG   128
#define CCAT    384
#define P1      256
#define P2      256
#define FRAMES  32          // B*T
#define EPS_D   1e-8f
#define EPS_BN  1e-5f

// ---------------- scratch (device globals, no runtime alloc) ----------------
__device__ __align__(16) int   g_idx[FRAMES * MPTS * 3];
__device__ __align__(16) float g_w  [FRAMES * MPTS * 3];
__device__ __align__(16) float g_ZT [(size_t)FRAMES * NPTS * P1];     // [f][n][o]
__device__ __align__(16) float g_y1 [(size_t)FRAMES * MPTS * P1];     // [f][m][o]
__device__ __align__(16) float g_y2 [(size_t)FRAMES * MPTS * P2];     // [f][m][o]
// fp16 weights (single precision-term), [k][n] layout (n contiguous)
__device__ __align__(16) __half g_W1a[CIN * P1];
__device__ __align__(16) __half g_W1b[CORIG * P1];
__device__ __align__(16) __half g_W2 [P1 * P2];
__device__ float g_sum1[TT * P1], g_sq1[TT * P1], g_a1[TT * P1], g_b1[TT * P1];
__device__ float g_sum2[TT * P2], g_sq2[TT * P2], g_a2[TT * P2], g_b2[TT * P2];

// ---------------- helpers ----------------
__device__ __forceinline__ uint32_t smem_u32(const void* p) {
    uint32_t a;
    asm("{ .reg .u64 t; cvta.to.shared.u64 t, %1; cvt.u32.u64 %0, t; }" : "=r"(a) : "l"(p));
    return a;
}

#define LDMX4(r, addr) \
    asm volatile("ldmatrix.sync.aligned.m8n8.x4.shared.b16 {%0,%1,%2,%3}, [%4];" \
        : "=r"((r)[0]), "=r"((r)[1]), "=r"((r)[2]), "=r"((r)[3]) : "r"(addr))

#define LDMX4T(r, addr) \
    asm volatile("ldmatrix.sync.aligned.m8n8.x4.trans.shared.b16 {%0,%1,%2,%3}, [%4];" \
        : "=r"((r)[0]), "=r"((r)[1]), "=r"((r)[2]), "=r"((r)[3]) : "r"(addr))

#define MMA_F16(d, a, b0, b1) \
    asm volatile("mma.sync.aligned.m16n8k16.row.col.f32.f16.f16.f32 " \
        "{%0,%1,%2,%3},{%4,%5,%6,%7},{%8,%9},{%0,%1,%2,%3};" \
        : "+f"((d)[0]), "+f"((d)[1]), "+f"((d)[2]), "+f"((d)[3]) \
        : "r"((a)[0]), "r"((a)[1]), "r"((a)[2]), "r"((a)[3]), "r"(b0), "r"(b1))

#define CP_ASYNC16(dst, src) \
    asm volatile("cp.async.cg.shared.global [%0], [%1], 16;" :: "r"(dst), "l"(src))
#define CP_COMMIT()  asm volatile("cp.async.commit_group;" ::: "memory")
#define CP_WAIT0()   asm volatile("cp.async.wait_group 0;" ::: "memory")
#define CP_WAIT1()   asm volatile("cp.async.wait_group 1;" ::: "memory")

// fp16 hi/lo split of two floats
__device__ __forceinline__ void split2(float a, float b, uint32_t& h, uint32_t& l) {
    __half2 hb = __floats2half2_rn(a, b);
    float2 hf = __half22float2(hb);
    __half2 lb = __floats2half2_rn(a - hf.x, b - hf.y);
    h = *reinterpret_cast<uint32_t*>(&hb);
    l = *reinterpret_cast<uint32_t*>(&lb);
}

// ---------------- prep ----------------
__global__ void prep_kernel(const float* __restrict__ W1, const float* __restrict__ W2) {
    int i = blockIdx.x * 256 + threadIdx.x;
    if (i < TT * P1) { g_sum1[i] = 0.f; g_sq1[i] = 0.f; g_sum2[i] = 0.f; g_sq2[i] = 0.f; }
    if (i < P1 * CCAT) {
        int o = i / CCAT, c = i % CCAT;
        __half h = __float2half_rn(W1[i]);
        if (c < CIN) g_W1a[c * P1 + o] = h;
        else         g_W1b[(c - CIN) * P1 + o] = h;
    }
    if (i < P2 * P1) {
        int o = i / P1, c = i % P1;
        g_W2[c * P2 + o] = __float2half_rn(W2[i]);
    }
}

// ---------------- three_nn: 2 m-points per thread (shared LDS amortized) ----------------
__global__ void knn_kernel(const float* __restrict__ xyzs, const float* __restrict__ oxyzs) {
    __shared__ float sx[NPTS], sy[NPTS], sz[NPTS];
    int f = blockIdx.y;
    const float* p = xyzs + (size_t)f * NPTS * 3;
    for (int i = threadIdx.x; i < NPTS; i += 256) {
        sx[i] = p[3 * i]; sy[i] = p[3 * i + 1]; sz[i] = p[3 * i + 2];
    }
    __syncthreads();
    int m1 = blockIdx.x * 256 + threadIdx.x;       // 0..2047
    int m2 = m1 + 2048;
    const float* q1 = oxyzs + ((size_t)f * MPTS + m1) * 3;
    const float* q2 = oxyzs + ((size_t)f * MPTS + m2) * 3;
    float ax = q1[0], ay = q1[1], az = q1[2];
    float cx = q2[0], cy = q2[1], cz = q2[2];
    float p0 = 1e30f, p1_ = 1e30f, p2_ = 1e30f;
    int   pi0 = 0,    pi1 = 0,    pi2 = 0;
    float r0 = 1e30f, r1 = 1e30f, r2 = 1e30f;
    int   ri0 = 0,    ri1 = 0,    ri2 = 0;
    #pragma unroll 4
    for (int n = 0; n < NPTS; n++) {
        float x = sx[n], y = sy[n], z = sz[n];
        float dx = ax - x, dy = ay - y, dz = az - z;
        float d = fmaf(dx, dx, fmaf(dy, dy, dz * dz));
        if (d < p2_) {
            if (d < p1_) {
                p2_ = p1_; pi2 = pi1;
                if (d < p0) { p1_ = p0; pi1 = pi0; p0 = d; pi0 = n; }
                else        { p1_ = d;  pi1 = n; }
            } else { p2_ = d; pi2 = n; }
        }
        float ex = cx - x, ey = cy - y, ez = cz - z;
        float e = fmaf(ex, ex, fmaf(ey, ey, ez * ez));
        if (e < r2) {
            if (e < r1) {
                r2 = r1; ri2 = ri1;
                if (e < r0) { r1 = r0; ri1 = ri0; r0 = e; ri0 = n; }
                else        { r1 = e;  ri1 = n; }
            } else { r2 = e; ri2 = n; }
        }
    }
    {
        float w0 = 1.f / (p0 + EPS_D), w1 = 1.f / (p1_ + EPS_D), w2 = 1.f / (p2_ + EPS_D);
        float inv = 1.f / (w0 + w1 + w2);
        size_t base = ((size_t)f * MPTS + m1) * 3;
        g_idx[base] = pi0; g_idx[base + 1] = pi1; g_idx[base + 2] = pi2;
        g_w[base] = w0 * inv; g_w[base + 1] = w1 * inv; g_w[base + 2] = w2 * inv;
    }
    {
        float w0 = 1.f / (r0 + EPS_D), w1 = 1.f / (r1 + EPS_D), w2 = 1.f / (r2 + EPS_D);
        float inv = 1.f / (w0 + w1 + w2);
        size_t base = ((size_t)f * MPTS + m2) * 3;
        g_idx[base] = ri0; g_idx[base + 1] = ri1; g_idx[base + 2] = ri2;
        g_w[base] = w0 * inv; g_w[base + 1] = w1 * inv; g_w[base + 2] = w2 * inv;
    }
}

// ---------------- HMMA GEMM: C[f][M][256] = (Ah+Al) @ Wfp16[K][256] ----------------
// CTA 64(M) x 128(N), 8 warps 2x4, warp tile 32x32, K chunk 32, dbl-buffered.
// 2-term fp16 split on A only; B single fp16 (weights). Per chunk/warp: 12 LDSM, 32 MMA.
// AMODE 0: A [k][m], cp.async + smem transform. AMODE 1: A [m][k], reg prefetch + BN1+ReLU.
// FUSE 1: epilogue combine gather(Z)+stats1 -> y1 ; FUSE 2: store + stats2

template <int K, int AMODE, int FUSE, int MTOT>
__device__ __forceinline__ void gemm_mma(const float* __restrict__ Aall,
                                         const __half* __restrict__ Ball,
                                         float* __restrict__ Call) {
    extern __shared__ char sm[];
    const uint32_t sbase = smem_u32(sm);
    constexpr int NC  = K / 32;
    constexpr int ABF = (AMODE == 1) ? 5120 : 4608;   // fp16 A buf stride (bytes)
    constexpr int AFB = 8704;                          // fp32 A buf stride (AMODE0)
    constexpr int OFF_AL = 2 * ABF;
    constexpr int OFF_AF = 4 * ABF;                    // AMODE0 only
    constexpr int OFF_BH = (AMODE == 0) ? (OFF_AF + 2 * AFB) : (4 * ABF);
    constexpr int OFF_SC = OFF_BH + 17408;             // AMODE1 only

    const int tid = threadIdx.x;
    const int l   = tid & 31;
    const int wid = tid >> 5;
    const int wm  = wid >> 2;       // 0..1
    const int wn  = wid & 3;        // 0..3
    const int f   = blockIdx.z, t = f & 3;
    const int bm  = blockIdx.y * 64;
    const int bn0 = blockIdx.x * 128;
    const float* A = Aall + (size_t)f * MTOT * K;
    float*       C = Call + (size_t)f * MTOT * 256;

    float* s_sc = (float*)(sm + OFF_SC);
    float* s_bi = (float*)(sm + OFF_SC + 1024);
    if (AMODE == 1) {
        s_sc[tid] = g_a1[t * 256 + tid];
        s_bi[tid] = g_b1[t * 256 + tid];
        __syncthreads();
    }

    // ldmatrix lane byte-offsets
    const uint32_t aoff = (AMODE == 1)
        ? (uint32_t)((l & 15) * 80 + (l >> 4) * 16 + wm * 2560)
        : (uint32_t)(((l & 7) + ((l >> 4) & 1) * 8) * 144 + ((l >> 3) & 1) * 16 + wm * 64);
    const uint32_t boff = (uint32_t)((((l & 7) + ((l >> 3) & 1) * 8) * 136 +
                                      (l >> 4) * 8 + wn * 32) * 2);

    float acc[2][4][4];
    #pragma unroll
    for (int i = 0; i < 2; i++)
        #pragma unroll
        for (int j = 0; j < 4; j++)
            #pragma unroll
            for (int k = 0; k < 4; k++) acc[i][j][k] = 0.f;

    float4 ra0, ra1;    // AMODE1 register prefetch

    auto issueB = [&](int kc, int bb) {
        int r  = tid >> 3;
        int ce = (tid & 7) * 16;
        const __half* sh = Ball + (size_t)(kc * 32 + r) * 256 + bn0 + ce;
        uint32_t dh = sbase + OFF_BH + bb * 8704 + (uint32_t)(r * 272 + ce * 2);
        CP_ASYNC16(dh,      sh);
        CP_ASYNC16(dh + 16, sh + 8);
    };
    // ---- AMODE0: A fp32 cp.async + transform ----
    auto issueAf = [&](int kc, int fb) {
        int r = tid >> 3;
        const float* s = A + (size_t)(kc * 32 + r) * MTOT + bm + (tid & 7) * 8;
        uint32_t dd = sbase + OFF_AF + fb * AFB + (uint32_t)(r * 272 + (tid & 7) * 32);
        CP_ASYNC16(dd, s);
        CP_ASYNC16(dd + 16, s + 4);
    };
    auto transform = [&](int fb, int ab) {
        #pragma unroll
        for (int g = 0; g < 2; g++) {
            int r = (tid >> 4) + g * 16;
            uint32_t srcb = (uint32_t)(OFF_AF + fb * AFB + r * 272 + (tid & 15) * 16);
            float4 v = *(const float4*)(sm + srcb);
            uint32_t h0, l0, h1, l1;
            split2(v.x, v.y, h0, l0); split2(v.z, v.w, h1, l1);
            uint32_t dst = (uint32_t)(ab * ABF + r * 144 + (tid & 15) * 8);
            *(uint2*)(sm + dst)          = make_uint2(h0, h1);
            *(uint2*)(sm + OFF_AL + dst) = make_uint2(l0, l1);
        }
    };
    // ---- AMODE1: register prefetch + fused BN ----
    auto loadA = [&](int kc) {
        const float* ap = A + (size_t)(bm + (tid >> 2)) * K + kc * 32 + (tid & 3) * 8;
        ra0 = *(const float4*)ap;
        ra1 = *(const float4*)(ap + 4);
    };
    auto storeA = [&](int buf, int kc) {
        float4 v0 = ra0, v1 = ra1;
        int cc = kc * 32 + (tid & 3) * 8;
        v0.x = fmaxf(0.f, fmaf(s_sc[cc + 0], v0.x, s_bi[cc + 0]));
        v0.y = fmaxf(0.f, fmaf(s_sc[cc + 1], v0.y, s_bi[cc + 1]));
        v0.z = fmaxf(0.f, fmaf(s_sc[cc + 2], v0.z, s_bi[cc + 2]));
        v0.w = fmaxf(0.f, fmaf(s_sc[cc + 3], v0.w, s_bi[cc + 3]));
        v1.x = fmaxf(0.f, fmaf(s_sc[cc + 4], v1.x, s_bi[cc + 4]));
        v1.y = fmaxf(0.f, fmaf(s_sc[cc + 5], v1.y, s_bi[cc + 5]));
        v1.z = fmaxf(0.f, fmaf(s_sc[cc + 6], v1.z, s_bi[cc + 6]));
        v1.w = fmaxf(0.f, fmaf(s_sc[cc + 7], v1.w, s_bi[cc + 7]));
        uint32_t h0, l0, h1, l1, h2, l2, h3, l3;
        split2(v0.x, v0.y, h0, l0); split2(v0.z, v0.w, h1, l1);
        split2(v1.x, v1.y, h2, l2); split2(v1.z, v1.w, h3, l3);
        uint32_t ao = (uint32_t)(buf * ABF + (tid >> 2) * 80 + (tid & 3) * 16);
        *(uint4*)(sm + ao)          = make_uint4(h0, h1, h2, h3);
        *(uint4*)(sm + OFF_AL + ao) = make_uint4(l0, l1, l2, l3);
    };
    // ---- compute: 2 split terms (ah*b, al*b) ----
    auto compute = [&](int buf) {
        #pragma unroll
        for (int ks = 0; ks < 2; ks++) {
            uint32_t ah[2][4], al[2][4], bh[2][4];
            #pragma unroll
            for (int mi = 0; mi < 2; mi++) {
                if (AMODE == 1) {
                    uint32_t ad = sbase + buf * ABF + aoff + mi * 1280 + ks * 32;
                    LDMX4(ah[mi], ad);
                    LDMX4(al[mi], ad + OFF_AL);
                } else {
                    uint32_t ad = sbase + buf * ABF + aoff + mi * 32 + ks * 2304;
                    LDMX4T(ah[mi], ad);
                    LDMX4T(al[mi], ad + OFF_AL);
                }
            }
            #pragma unroll
            for (int nf = 0; nf < 2; nf++) {
                uint32_t bd = sbase + OFF_BH + buf * 8704 + boff + nf * 32 + ks * 4352;
                LDMX4T(bh[nf], bd);
            }
            #pragma unroll
            for (int mi = 0; mi < 2; mi++)
                #pragma unroll
                for (int nf = 0; nf < 2; nf++) {
                    MMA_F16(acc[mi][nf * 2],     ah[mi], bh[nf][0], bh[nf][1]);
                    MMA_F16(acc[mi][nf * 2 + 1], ah[mi], bh[nf][2], bh[nf][3]);
                }
            #pragma unroll
            for (int mi = 0; mi < 2; mi++)
                #pragma unroll
                for (int nf = 0; nf < 2; nf++) {
                    MMA_F16(acc[mi][nf * 2],     al[mi], bh[nf][0], bh[nf][1]);
                    MMA_F16(acc[mi][nf * 2 + 1], al[mi], bh[nf][2], bh[nf][3]);
                }
        }
    };

    if (AMODE == 0) {
        issueAf(0, 0); CP_COMMIT();
        issueB(0, 0); issueAf(1, 1); CP_COMMIT();
        CP_WAIT1();
        __syncthreads();
        transform(0, 0);
        for (int kc = 0; kc < NC; kc++) {
            CP_WAIT0();
            __syncthreads();
            if (kc + 1 < NC) {
                transform((kc + 1) & 1, (kc + 1) & 1);
                issueB(kc + 1, (kc + 1) & 1);
                if (kc + 2 < NC) issueAf(kc + 2, kc & 1);
                CP_COMMIT();
            }
            compute(kc & 1);
        }
    } else {
        issueB(0, 0); CP_COMMIT();
        loadA(0); storeA(0, 0);
        CP_WAIT0();
        __syncthreads();
        for (int kc = 0; kc < NC; kc++) {
            if (kc + 1 < NC) {
                issueB(kc + 1, (kc + 1) & 1); CP_COMMIT();
                loadA(kc + 1);
            }
            compute(kc & 1);
            if (kc + 1 < NC) {
                storeA((kc + 1) & 1, kc + 1);
                CP_WAIT0();
                __syncthreads();
            }
        }
    }

    if (FUSE == 1) {
        // stage acc tile to smem fp32 [64][136], then combine gather(Z)+stats1 -> y1
        __syncthreads();
        float* smf = (float*)sm;
        #pragma unroll
        for (int ni = 0; ni < 4; ni++) {
            int c = wn * 32 + ni * 8 + (l & 3) * 2;
            #pragma unroll
            for (int mi = 0; mi < 2; mi++) {
                int r = wm * 32 + mi * 16 + (l >> 2);
                *(float2*)&smf[r * 136 + c]       = make_float2(acc[mi][ni][0], acc[mi][ni][1]);
                *(float2*)&smf[(r + 8) * 136 + c] = make_float2(acc[mi][ni][2], acc[mi][ni][3]);
            }
        }
        __syncthreads();
        const int oc = tid & 127, half = tid >> 7;
        const int o  = bn0 + oc;
        const float* Z = g_ZT + (size_t)f * NPTS * 256;
        float s = 0.f, q = 0.f;
        #pragma unroll 4
        for (int rr = 0; rr < 32; rr++) {
            int r = half * 32 + rr;
            int m = bm + r;
            size_t ib = ((size_t)f * MPTS + m) * 3;
            int   i0 = g_idx[ib], i1 = g_idx[ib + 1], i2 = g_idx[ib + 2];
            float w0 = g_w[ib],   w1 = g_w[ib + 1],   w2 = g_w[ib + 2];
            float v = smf[r * 136 + oc];
            v = fmaf(w0, Z[(size_t)i0 * 256 + o], v);
            v = fmaf(w1, Z[(size_t)i1 * 256 + o], v);
            v = fmaf(w2, Z[(size_t)i2 * 256 + o], v);
            g_y1[((size_t)f * MPTS + m) * 256 + o] = v;
            s += v; q = fmaf(v, v, q);
        }
        atomicAdd(&g_sum1[t * 256 + o], s);
        atomicAdd(&g_sq1 [t * 256 + o], q);
    } else {
        #pragma unroll
        for (int ni = 0; ni < 4; ni++) {
            int col = bn0 + wn * 32 + ni * 8 + (l & 3) * 2;
            float s0 = 0.f, q0 = 0.f, s1 = 0.f, q1 = 0.f;
            #pragma unroll
            for (int mi = 0; mi < 2; mi++) {
                int row = bm + wm * 32 + mi * 16 + (l >> 2);
                float v0 = acc[mi][ni][0], v1 = acc[mi][ni][1];
                float v2 = acc[mi][ni][2], v3 = acc[mi][ni][3];
                float* cp = C + (size_t)row * 256 + col;
                *(float2*)cp          = make_float2(v0, v1);
                *(float2*)(cp + 2048) = make_float2(v2, v3);
                if (FUSE == 2) {
                    s0 += v0 + v2; s1 += v1 + v3;
                    q0 += fmaf(v0, v0, v2 * v2);
                    q1 += fmaf(v1, v1, v3 * v3);
                }
            }
            if (FUSE == 2) {
                #pragma unroll
                for (int d = 4; d < 32; d <<= 1) {
                    s0 += __shfl_xor_sync(0xffffffffu, s0, d);
                    s1 += __shfl_xor_sync(0xffffffffu, s1, d);
                    q0 += __shfl_xor_sync(0xffffffffu, q0, d);
                    q1 += __shfl_xor_sync(0xffffffffu, q1, d);
                }
                if (l < 4) {
                    atomicAdd(&g_sum2[t * 256 + col],     s0);
                    atomicAdd(&g_sum2[t * 256 + col + 1], s1);
                    atomicAdd(&g_sq2 [t * 256 + col],     q0);
                    atomicAdd(&g_sq2 [t * 256 + col + 1], q1);
                }
            }
        }
    }
}

#define SMEM_A0 53248     // 4*4608 + 2*8704 (A fp32) + 2*8704 (B)
#define SMEM_A1 39936     // 4*5120 + 2*8704 (B) + 2048 (BN coefs)

__global__ void __launch_bounds__(256, 3) gemmZ_mma(const float* __restrict__ feats) {
    gemm_mma<CIN, 0, 0, NPTS>(feats, g_W1a, g_ZT);
}
__global__ void __launch_bounds__(256, 3) gemmB_mma(const float* __restrict__ ofeat) {
    gemm_mma<CORIG, 0, 1, MPTS>(ofeat, g_W1b, g_y1);
}
__global__ void __launch_bounds__(256, 3) gemm2_mma() {
    gemm_mma<P1, 1, 2, MPTS>(g_y1, g_W2, g_y2);
}

// ---------------- finalize BN coefficients ----------------
__global__ void finalize_kernel(int which, const float* __restrict__ gamma,
                                const float* __restrict__ beta) {
    int i = blockIdx.x * 256 + threadIdx.x;
    if (i >= TT * P1) return;
    const float rcnt = 1.0f / (float)(BB * MPTS);
    float sum = (which == 1) ? g_sum1[i] : g_sum2[i];
    float sq  = (which == 1) ? g_sq1[i]  : g_sq2[i];
    float mean = sum * rcnt;
    float var  = fmaf(-mean, mean, sq * rcnt);
    int o = i & 255;
    float a = gamma[o] * rsqrtf(var + EPS_BN);
    float b = fmaf(-mean, a, beta[o]);
    if (which == 1) { g_a1[i] = a; g_b1[i] = b; }
    else            { g_a2[i] = a; g_b2[i] = b; }
}

// ---------------- output: BN2+ReLU + transpose [f][m][o] -> [f][o][m] ----------------
__global__ void output_kernel(float* __restrict__ out) {
    __shared__ float tile[32][33];
    int f = blockIdx.z, t = f & 3;
    int m0 = blockIdx.x * 32, o0 = blockIdx.y * 32;
    int tx = threadIdx.x, ty = threadIdx.y;
    #pragma unroll
    for (int i = ty; i < 32; i += 8) {
        int o = o0 + tx;
        float v = g_y2[((size_t)f * MPTS + m0 + i) * P2 + o];
        tile[i][tx] = fmaxf(0.f, fmaf(g_a2[t * P2 + o], v, g_b2[t * P2 + o]));
    }
    __syncthreads();
    #pragma unroll
    for (int i = ty; i < 32; i += 8)
        out[((size_t)f * P2 + o0 + i) * MPTS + m0 + tx] = tile[tx][i];
}

// ---------------- launch ----------------
extern "C" void kernel_launch(void* const* d_in, const int* in_sizes, int n_in,
                              void* d_out, int out_size) {
    const float* xyzs   = (const float*)d_in[0];
    const float* oxyzs  = (const float*)d_in[1];
    const float* feats  = (const float*)d_in[2];
    const float* ofeat  = (const float*)d_in[3];
    const float* W1     = (const float*)d_in[4];
    const float* gamma1 = (const float*)d_in[5];
    const float* beta1  = (const float*)d_in[6];
    const float* W2     = (const float*)d_in[7];
    const float* gamma2 = (const float*)d_in[8];
    const float* beta2  = (const float*)d_in[9];
    float* out = (float*)d_out;

    (void)cudaFuncSetAttribute(gemmZ_mma, cudaFuncAttributeMaxDynamicSharedMemorySize, SMEM_A0);
    (void)cudaFuncSetAttribute(gemmB_mma, cudaFuncAttributeMaxDynamicSharedMemorySize, SMEM_A0);
    (void)cudaFuncSetAttribute(gemm2_mma, cudaFuncAttributeMaxDynamicSharedMemorySize, SMEM_A1);

    const int xyz_elems = FRAMES * MPTS * 3;
    const int x_elems   = FRAMES * P2 * MPTS;
    float* out_x = out;
    if (out_size >= xyz_elems + x_elems) {
        cudaMemcpyAsync(out, oxyzs, (size_t)xyz_elems * sizeof(float),
                        cudaMemcpyDeviceToDevice, 0);
        out_x = out + xyz_elems;
    }

    prep_kernel<<<384, 256>>>(W1, W2);
    knn_kernel<<<dim3(MPTS / 512, FRAMES), 256>>>(xyzs, oxyzs);

    gemmZ_mma<<<dim3(2, NPTS / 64, FRAMES), 256, SMEM_A0>>>(feats);   // Z = feats^T @ W1a
    gemmB_mma<<<dim3(2, MPTS / 64, FRAMES), 256, SMEM_A0>>>(ofeat);   // y1 + gather(Z); stats1
    finalize_kernel<<<4, 256>>>(1, gamma1, beta1);

    gemm2_mma<<<dim3(2, MPTS / 64, FRAMES), 256, SMEM_A1>>>();        // y2 = relu(bn1(y1)) @ W2; stats2
    finalize_kernel<<<4, 256>>>(2, gamma2, beta2);

    output_kernel<<<dim3(MPTS / 32, P2 / 32, FRAMES), dim3(32, 8)>>>(out_x);
}